// round 10
// baseline (speedup 1.0000x reference)
#include <cuda_runtime.h>
#include <math.h>
#include <stdint.h>

#define NB 16
#define D_NEED 29      // frames d = 31..59
#define D_OFF 31
#define T_NEED 15      // t = 45..59
#define BLK_PER_B 145  // 145 blocks * 500 outputs = 72500 = 29*2500 per batch

// scratch (no allocations allowed)
__device__ float g_s1[NB * D_NEED * 2500];   // spatial-conv output [b][29][50x50]
__device__ int   g_cnt[NB];                  // per-batch completion counters (zero-init)

// ---------------------------------------------------------------------------
// Fully fused kernel. grid = (145, 16), block = 512 (500 active in phase A).
// Phase A: direct 5x5/stride-5 spatial conv (one output/thread, coalesced,
//          every input byte read exactly once, no barriers in the hot path).
// Tail:    the last-finishing block of each batch (atomicAdd == 144) runs
//          temporal conv + ReLU -> last conv -> ama/gang cone -> out[b],
//          entirely in smem, overlapping other batches' phase A.
// ---------------------------------------------------------------------------
__global__ void __launch_bounds__(512) kFused(
    const float* __restrict__ x,
    const float* __restrict__ sw,
    const float* __restrict__ tw_g,
    const float* __restrict__ lw_g,
    const float* __restrict__ acw,
    const float* __restrict__ akw,
    const float* __restrict__ akb,
    const float* __restrict__ alw,
    const float* __restrict__ gcw,
    const float* __restrict__ gkw,
    const float* __restrict__ gkb,
    const float* __restrict__ gcolw,
    float* __restrict__ out)
{
    __shared__ float sfirst[2][T_NEED * 250];  // two row-groups at a time
    __shared__ float sflat[T_NEED * 100];
    __shared__ float tw[15];
    __shared__ float lw[25];
    __shared__ float red[49];
    __shared__ int   isLast;

    const int b   = blockIdx.y;
    const int tid = threadIdx.x;

    // ---------------- Phase A: spatial conv, 500 outputs ----------------
    if (tid < 500) {
        const int fid  = blockIdx.x * 500 + tid;      // 0..72499 within batch
        const int dIdx = fid / 2500;
        const int pix  = fid % 2500;
        const int orow = pix / 50;
        const int ocol = pix % 50;

        const float* p = x + (size_t)(b * 60 + D_OFF + dIdx) * 62500u
                           + orow * 1250 + ocol * 5;

        float v[25];
        #pragma unroll
        for (int i = 0; i < 5; i++)
            #pragma unroll
            for (int j = 0; j < 5; j++)
                v[i * 5 + j] = __ldg(p + i * 250 + j);

        float a0 = 0.f, a1 = 0.f, a2 = 0.f, a3 = 0.f, a4 = 0.f;
        #pragma unroll
        for (int j = 0; j < 5; j++) {
            a0 = fmaf(sw[0 * 5 + j], v[0 * 5 + j], a0);
            a1 = fmaf(sw[1 * 5 + j], v[1 * 5 + j], a1);
            a2 = fmaf(sw[2 * 5 + j], v[2 * 5 + j], a2);
            a3 = fmaf(sw[3 * 5 + j], v[3 * 5 + j], a3);
            a4 = fmaf(sw[4 * 5 + j], v[4 * 5 + j], a4);
        }
        g_s1[b * (D_NEED * 2500) + fid] = ((a0 + a1) + (a2 + a3)) + a4;
    }

    // ---------------- last-block election ----------------
    __threadfence();                       // publish g_s1 writes
    __syncthreads();
    if (tid == 0) {
        const int prev = atomicAdd(&g_cnt[b], 1);
        isLast = (prev == BLK_PER_B - 1);
    }
    __syncthreads();
    if (!isLast) return;
    __threadfence();                       // order counter read before g_s1 reads

    // ---------------- Phase B: tail for batch b ----------------
    if (tid < 15) tw[tid] = tw_g[tid];
    if (tid >= 32 && tid < 57) lw[tid - 32] = lw_g[tid - 32];
    __syncthreads();

    #pragma unroll
    for (int p5 = 0; p5 < 5; p5++) {       // 2 row-groups per pass
        if (tid < 500) {
            const int sg  = tid / 250;     // 0 or 1
            const int col = tid % 250;
            const int grp = p5 * 2 + sg;   // global row-group 0..9
            const float* src = g_s1 + (size_t)b * (D_NEED * 2500) + grp * 250 + col;
            float v[D_NEED];
            #pragma unroll
            for (int d = 0; d < D_NEED; d++) v[d] = src[d * 2500];
            #pragma unroll
            for (int t = 0; t < T_NEED; t++) {
                float acc = 0.f;
                #pragma unroll
                for (int k = 0; k < 15; k++)
                    acc = fmaf(tw[k], v[t + k], acc);
                sfirst[sg][t * 250 + col] = fmaxf(acc, 0.f);
            }
        }
        __syncthreads();

        if (tid < 300) {                   // 2 groups x 15 t x 10 cols
            const int sg  = tid / 150;
            const int r   = tid % 150;
            const int t   = r / 10, c = r % 10;
            const int grp = p5 * 2 + sg;
            const float* q = &sfirst[sg][t * 250 + c * 5];
            float acc = 0.f;
            #pragma unroll
            for (int i = 0; i < 5; i++)
                #pragma unroll
                for (int j = 0; j < 5; j++)
                    acc = fmaf(lw[i * 5 + j], q[i * 50 + j], acc);
            sflat[t * 100 + grp * 10 + c] = acc;
        }
        __syncthreads();
    }

    // ama/gang cone at t=59
    if (tid < 49) {
        const float ac = acw[0], al = alw[0], gc = gcw[0];
        const int ja = 2 * tid;
        const int jg = (2 * tid + 25) % 100;
        float a = akb[0];
        float g = gkb[0];
        #pragma unroll
        for (int k = 0; k < 15; k++) {
            a = fmaf(akw[k], ac * sflat[k * 100 + ja], a);
            g = fmaf(gkw[k], gc * sflat[k * 100 + jg], g);
        }
        const float amo = al / (1.f + expf(-a));
        const float val = 1.f / (1.f + expf(-(g - fabsf(amo))));
        red[tid] = gcolw[tid] * val;
    }
    __syncthreads();

    if (tid == 0) {
        float s = 0.f;
        #pragma unroll
        for (int j = 0; j < 49; j++) s += red[j];
        out[b] = s;
        g_cnt[b] = 0;                      // reset for deterministic graph replay
    }
}

// ---------------------------------------------------------------------------
extern "C" void kernel_launch(void* const* d_in, const int* in_sizes, int n_in,
                              void* d_out, int out_size)
{
    const float* x          = (const float*)d_in[0];
    const float* space_w    = (const float*)d_in[1];
    const float* temporal_w = (const float*)d_in[2];
    const float* last_w     = (const float*)d_in[3];
    const float* ama_create = (const float*)d_in[4];
    const float* ama_kern   = (const float*)d_in[5];
    const float* ama_kern_b = (const float*)d_in[6];
    const float* ama_alpha  = (const float*)d_in[7];
    const float* gang_create= (const float*)d_in[8];
    const float* gang_kern  = (const float*)d_in[9];
    const float* gang_kern_b= (const float*)d_in[10];
    const float* gang_col   = (const float*)d_in[11];
    float* out = (float*)d_out;

    dim3 grid(BLK_PER_B, NB);
    kFused<<<grid, 512>>>(x, space_w, temporal_w, last_w,
                          ama_create, ama_kern, ama_kern_b, ama_alpha,
                          gang_create, gang_kern, gang_kern_b, gang_col, out);
}

// round 11
// speedup vs baseline: 1.0576x; 1.0576x over previous
#include <cuda_runtime.h>
#include <math.h>
#include <stdint.h>

#define NB 16
#define D_NEED 29      // frames d = 31..59
#define D_OFF 31
#define T_NEED 15      // t = 45..59

#define N_OUT (NB * D_NEED * 2500)   // 1,160,000 spatial-conv outputs

// scratch (no allocations allowed)
__device__ float g_s1[NB * D_NEED * 2500];     // spatial-conv output [b][29][50x50]
__device__ float g_flat[NB * T_NEED * 100];    // last-conv output, 100 per (b,t)
__device__ int   g_cnt[NB];                    // per-batch completion counters (zero-init)

// ---------------------------------------------------------------------------
// Kernel A: 5x5 stride-5 spatial conv on frames 31..59 — DIRECT, no smem.
// 1 thread = 1 output pixel; fully coalesced; every input byte read once;
// MLP=25 per thread; zero barriers -> uniform DRAM demand. (R9 verbatim.)
// ---------------------------------------------------------------------------
__global__ void __launch_bounds__(256) kA(const float* __restrict__ x,
                                          const float* __restrict__ sw)
{
    const int id = blockIdx.x * 256 + threadIdx.x;
    if (id >= N_OUT) return;

    const int ocol = id % 50;
    const int orow = (id / 50) % 50;
    const int f    = id / 2500;             // 0..463 = b*29 + dIdx
    const int b    = f / D_NEED;
    const int dIdx = f % D_NEED;

    const float* p = x + (size_t)(b * 60 + D_OFF + dIdx) * 62500u
                       + orow * 1250 + ocol * 5;

    float v[25];
    #pragma unroll
    for (int i = 0; i < 5; i++)
        #pragma unroll
        for (int j = 0; j < 5; j++)
            v[i * 5 + j] = __ldg(p + i * 250 + j);

    float a0 = 0.f, a1 = 0.f, a2 = 0.f, a3 = 0.f, a4 = 0.f;
    #pragma unroll
    for (int j = 0; j < 5; j++) {
        a0 = fmaf(sw[0 * 5 + j],  v[0 * 5 + j], a0);
        a1 = fmaf(sw[1 * 5 + j],  v[1 * 5 + j], a1);
        a2 = fmaf(sw[2 * 5 + j],  v[2 * 5 + j], a2);
        a3 = fmaf(sw[3 * 5 + j],  v[3 * 5 + j], a3);
        a4 = fmaf(sw[4 * 5 + j],  v[4 * 5 + j], a4);
    }
    g_s1[id] = ((a0 + a1) + (a2 + a3)) + a4;
}

// ---------------------------------------------------------------------------
// Kernel BC: temporal conv + ReLU + last conv; last block per batch also
// runs the ama/gang cone and writes out[b].  grid = (10, 16), block = 256.
// ---------------------------------------------------------------------------
__global__ void __launch_bounds__(256) kBC(const float* __restrict__ tw_g,
                                           const float* __restrict__ lw_g,
                                           const float* __restrict__ acw,
                                           const float* __restrict__ akw,
                                           const float* __restrict__ akb,
                                           const float* __restrict__ alw,
                                           const float* __restrict__ gcw,
                                           const float* __restrict__ gkw,
                                           const float* __restrict__ gkb,
                                           const float* __restrict__ gcolw,
                                           float* __restrict__ out)
{
    __shared__ float sfirst[T_NEED * 250];   // [t][5 rows x 50 cols]
    __shared__ float tw[15];
    __shared__ float lw[25];
    __shared__ float red[49];
    __shared__ int   isLast;
    const int grp = blockIdx.x;   // output row h = grp
    const int b   = blockIdx.y;
    const int tid = threadIdx.x;

    if (tid < 15) tw[tid] = tw_g[tid];
    if (tid >= 32 && tid < 57) lw[tid - 32] = lw_g[tid - 32];
    __syncthreads();

    // temporal conv + relu (g_s1 read exactly once, coalesced)
    if (tid < 250) {
        const float* src = g_s1 + (size_t)b * (D_NEED * 2500) + grp * 250 + tid;
        float v[D_NEED];
        #pragma unroll
        for (int d = 0; d < D_NEED; d++) v[d] = src[d * 2500];
        #pragma unroll
        for (int t = 0; t < T_NEED; t++) {
            float acc = 0.f;
            #pragma unroll
            for (int k = 0; k < 15; k++)
                acc = fmaf(tw[k], v[t + k], acc);
            sfirst[t * 250 + tid] = fmaxf(acc, 0.f);
        }
    }
    __syncthreads();

    // last conv -> g_flat
    if (tid < 150) {
        const int t = tid / 10, c = tid % 10;
        const float* p = sfirst + t * 250 + c * 5;
        float acc = 0.f;
        #pragma unroll
        for (int i = 0; i < 5; i++)
            #pragma unroll
            for (int j = 0; j < 5; j++)
                acc = fmaf(lw[i * 5 + j], p[i * 50 + j], acc);
        g_flat[(b * T_NEED + t) * 100 + grp * 10 + c] = acc;
    }

    // -------- last-block election for batch b --------
    __threadfence();
    __syncthreads();
    if (tid == 0) {
        const int prev = atomicAdd(&g_cnt[b], 1);
        isLast = (prev == 9);
    }
    __syncthreads();
    if (!isLast) return;
    __threadfence();

    // -------- kC tail: ama/gang cone at t=59 --------
    if (tid < 49) {
        const float ac = acw[0], al = alw[0], gc = gcw[0];
        const int ja = 2 * tid;
        const int jg = (2 * tid + 25) % 100;
        float a = akb[0];
        float g = gkb[0];
        const float* fl = g_flat + b * (T_NEED * 100);
        #pragma unroll
        for (int k = 0; k < 15; k++) {
            a = fmaf(akw[k], ac * fl[k * 100 + ja], a);
            g = fmaf(gkw[k], gc * fl[k * 100 + jg], g);
        }
        const float amo = al / (1.f + expf(-a));
        const float val = 1.f / (1.f + expf(-(g - fabsf(amo))));
        red[tid] = gcolw[tid] * val;
    }
    __syncthreads();

    if (tid == 0) {
        float s = 0.f;
        #pragma unroll
        for (int j = 0; j < 49; j++) s += red[j];
        out[b] = s;
        g_cnt[b] = 0;                      // reset for deterministic graph replay
    }
}

// ---------------------------------------------------------------------------
extern "C" void kernel_launch(void* const* d_in, const int* in_sizes, int n_in,
                              void* d_out, int out_size)
{
    const float* x          = (const float*)d_in[0];
    const float* space_w    = (const float*)d_in[1];
    const float* temporal_w = (const float*)d_in[2];
    const float* last_w     = (const float*)d_in[3];
    const float* ama_create = (const float*)d_in[4];
    const float* ama_kern   = (const float*)d_in[5];
    const float* ama_kern_b = (const float*)d_in[6];
    const float* ama_alpha  = (const float*)d_in[7];
    const float* gang_create= (const float*)d_in[8];
    const float* gang_kern  = (const float*)d_in[9];
    const float* gang_kern_b= (const float*)d_in[10];
    const float* gang_col   = (const float*)d_in[11];
    float* out = (float*)d_out;

    kA<<<(N_OUT + 255) / 256, 256>>>(x, space_w);

    dim3 gBC(10, NB);
    kBC<<<gBC, 256>>>(temporal_w, last_w,
                      ama_create, ama_kern, ama_kern_b, ama_alpha,
                      gang_create, gang_kern, gang_kern_b, gang_col, out);
}

// round 12
// speedup vs baseline: 1.3145x; 1.2429x over previous
#include <cuda_runtime.h>
#include <math.h>
#include <stdint.h>

#define NB 16
#define D_NEED 29      // frames d = 31..59
#define D_OFF 31
#define T_NEED 15      // t = 45..59

#define BANDS 11600         // NB * 725 bands of 10 input rows
#define GRID_A 888          // 6 blocks per SM
#define STAGES 2
#define BAND_FLOATS 2500    // 10 rows * 250 cols
#define BAND_BYTES 10000    // multiple of 16

// scratch (no allocations allowed)
__device__ float g_s1[NB * D_NEED * 2500];     // spatial-conv output [b][29][50x50]
__device__ float g_flat[NB * T_NEED * 100];    // last-conv output, 100 per (b,t)

__device__ __forceinline__ unsigned su32(const void* p) {
    return (unsigned)__cvta_generic_to_shared(p);
}

__device__ __forceinline__ void mbar_wait(unsigned mbar, unsigned phase) {
    unsigned done = 0;
    do {
        asm volatile(
            "{\n\t.reg .pred p;\n\t"
            "mbarrier.try_wait.parity.shared.b64 p, [%1], %2, 10000000;\n\t"
            "selp.b32 %0, 1, 0, p;\n\t}"
            : "=r"(done) : "r"(mbar), "r"(phase) : "memory");
    } while (!done);
}

// ---------------------------------------------------------------------------
// Kernel A: 5x5 stride-5 spatial conv on frames 31..59.  (R7 config verbatim)
// 888 blocks (6/SM), 128 threads, 2-stage x 10 KB TMA pipeline (20 KB smem).
// Band id -> b = id/725, rem = id%725 : 10 input rows, 100 outputs.
// 6 independent blocks per SM -> statistical multiplexing of TMA waits.
// ---------------------------------------------------------------------------
__global__ void __launch_bounds__(128) kA(const float* __restrict__ x,
                                          const float* __restrict__ sw)
{
    extern __shared__ float dbuf[];                 // STAGES * 2500 floats
    __shared__ unsigned long long mbar[STAGES];
    __shared__ float w[25];
    const int tid = threadIdx.x;

    unsigned mb[STAGES], bb[STAGES];
    #pragma unroll
    for (int s = 0; s < STAGES; s++) {
        mb[s] = su32(&mbar[s]);
        bb[s] = su32(dbuf + s * BAND_FLOATS);
    }

    if (tid == 0) {
        #pragma unroll
        for (int s = 0; s < STAGES; s++)
            asm volatile("mbarrier.init.shared.b64 [%0], 1;" :: "r"(mb[s]) : "memory");
        asm volatile("fence.proxy.async.shared::cta;" ::: "memory");
    }
    if (tid < 25) w[tid] = sw[tid];
    __syncthreads();

    const int nMine = (BANDS - 1 - (int)blockIdx.x) / GRID_A + 1;

    auto issueTMA = [&](int j) {
        const int id  = blockIdx.x + j * GRID_A;
        const int b   = id / 725;
        const int rem = id % 725;
        const float* src = x + (size_t)(b * 60 + D_OFF) * 62500u
                             + (size_t)rem * BAND_FLOATS;
        const int s = j & (STAGES - 1);
        asm volatile("mbarrier.arrive.expect_tx.shared.b64 _, [%0], %1;"
                     :: "r"(mb[s]), "n"(BAND_BYTES) : "memory");
        asm volatile("cp.async.bulk.shared::cta.global.mbarrier::complete_tx::bytes "
                     "[%0], [%1], %2, [%3];"
                     :: "r"(bb[s]), "l"(src), "n"(BAND_BYTES), "r"(mb[s]) : "memory");
    };

    if (tid == 0 && nMine > 0) issueTMA(0);

    for (int j = 0; j < nMine; j++) {
        // issue band j+1: its buffer was freed by iteration j-1's sync
        if (tid == 0 && j + 1 < nMine) issueTMA(j + 1);

        const int s = j & (STAGES - 1);
        mbar_wait(mb[s], (j >> 1) & 1);

        const int id = blockIdx.x + j * GRID_A;
        if (tid < 100) {
            const float* p = dbuf + s * BAND_FLOATS
                           + (tid / 50) * 1250 + (tid % 50) * 5;
            float acc = 0.f;
            #pragma unroll
            for (int i = 0; i < 5; i++)
                #pragma unroll
                for (int jj = 0; jj < 5; jj++)
                    acc = fmaf(w[i * 5 + jj], p[i * 250 + jj], acc);
            g_s1[id * 100 + tid] = acc;
        }
        __syncthreads();                 // all reads of buffer s done
    }
}

// ---------------------------------------------------------------------------
// Kernel B: temporal 15-tap conv + ReLU + 5x5/stride-5 last conv.
// grid = (10 row-groups, 16 batches), block = 256. Reads g_s1 exactly once.
// ---------------------------------------------------------------------------
__global__ void __launch_bounds__(256) kB(const float* __restrict__ tw_g,
                                          const float* __restrict__ lw_g)
{
    __shared__ float sfirst[T_NEED * 250];   // [t][5 rows x 50 cols]
    __shared__ float tw[15];
    __shared__ float lw[25];
    const int grp = blockIdx.x;   // output row h = grp, pixels grp*250..+249
    const int b   = blockIdx.y;
    const int tid = threadIdx.x;

    if (tid < 15) tw[tid] = tw_g[tid];
    if (tid >= 32 && tid < 57) lw[tid - 32] = lw_g[tid - 32];
    __syncthreads();

    if (tid < 250) {
        const float* src = g_s1 + (size_t)b * (D_NEED * 2500) + grp * 250 + tid;
        float v[D_NEED];
        #pragma unroll
        for (int d = 0; d < D_NEED; d++) v[d] = src[d * 2500];
        #pragma unroll
        for (int t = 0; t < T_NEED; t++) {
            float acc = 0.f;
            #pragma unroll
            for (int k = 0; k < 15; k++)
                acc = fmaf(tw[k], v[t + k], acc);
            sfirst[t * 250 + tid] = fmaxf(acc, 0.f);
        }
    }
    __syncthreads();

    if (tid < 150) {
        const int t = tid / 10, c = tid % 10;
        const float* p = sfirst + t * 250 + c * 5;
        float acc = 0.f;
        #pragma unroll
        for (int i = 0; i < 5; i++)
            #pragma unroll
            for (int j = 0; j < 5; j++)
                acc = fmaf(lw[i * 5 + j], p[i * 50 + j], acc);
        g_flat[(b * T_NEED + t) * 100 + grp * 10 + c] = acc;
    }
}

// ---------------------------------------------------------------------------
// Kernel C: ama/gang cone at t=59 + 49-tap dot product. grid = 16, block = 64.
// ---------------------------------------------------------------------------
__global__ void __launch_bounds__(64) kC(const float* __restrict__ acw,
                                         const float* __restrict__ akw,
                                         const float* __restrict__ akb,
                                         const float* __restrict__ alw,
                                         const float* __restrict__ gcw,
                                         const float* __restrict__ gkw,
                                         const float* __restrict__ gkb,
                                         const float* __restrict__ gcolw,
                                         float* __restrict__ out)
{
    __shared__ float fl[T_NEED * 100];
    __shared__ float red[49];
    const int b   = blockIdx.x;
    const int tid = threadIdx.x;

    for (int i = tid; i < T_NEED * 100; i += 64)
        fl[i] = g_flat[b * (T_NEED * 100) + i];
    __syncthreads();

    if (tid < 49) {
        const float ac = acw[0], al = alw[0], gc = gcw[0];
        const int ja = 2 * tid;
        const int jg = (2 * tid + 25) % 100;
        float a = akb[0];
        float g = gkb[0];
        #pragma unroll
        for (int k = 0; k < 15; k++) {
            a = fmaf(akw[k], ac * fl[k * 100 + ja], a);
            g = fmaf(gkw[k], gc * fl[k * 100 + jg], g);
        }
        const float amo = al / (1.f + expf(-a));
        const float val = 1.f / (1.f + expf(-(g - fabsf(amo))));
        red[tid] = gcolw[tid] * val;
    }
    __syncthreads();

    if (tid == 0) {
        float s = 0.f;
        #pragma unroll
        for (int j = 0; j < 49; j++) s += red[j];
        out[b] = s;
    }
}

// ---------------------------------------------------------------------------
extern "C" void kernel_launch(void* const* d_in, const int* in_sizes, int n_in,
                              void* d_out, int out_size)
{
    const float* x          = (const float*)d_in[0];
    const float* space_w    = (const float*)d_in[1];
    const float* temporal_w = (const float*)d_in[2];
    const float* last_w     = (const float*)d_in[3];
    const float* ama_create = (const float*)d_in[4];
    const float* ama_kern   = (const float*)d_in[5];
    const float* ama_kern_b = (const float*)d_in[6];
    const float* ama_alpha  = (const float*)d_in[7];
    const float* gang_create= (const float*)d_in[8];
    const float* gang_kern  = (const float*)d_in[9];
    const float* gang_kern_b= (const float*)d_in[10];
    const float* gang_col   = (const float*)d_in[11];
    float* out = (float*)d_out;

    const int dynA = STAGES * BAND_BYTES;   // 20000 bytes
    cudaFuncSetAttribute(kA, cudaFuncAttributeMaxDynamicSharedMemorySize, dynA);

    kA<<<GRID_A, 128, dynA>>>(x, space_w);

    dim3 gB(10, NB);
    kB<<<gB, 256>>>(temporal_w, last_w);

    kC<<<NB, 64>>>(ama_create, ama_kern, ama_kern_b, ama_alpha,
                   gang_create, gang_kern, gang_kern_b, gang_col, out);
}

// round 13
// speedup vs baseline: 1.4189x; 1.0794x over previous
#include <cuda_runtime.h>
#include <math.h>
#include <stdint.h>

#define NB 16
#define D_NEED 29      // frames d = 31..59
#define D_OFF 31
#define T_NEED 15      // t = 45..59

#define N_OUT (NB * D_NEED * 2500)   // 1,160,000 spatial-conv outputs

// scratch (no allocations allowed)
__device__ float g_s1[NB * D_NEED * 2500];   // spatial-conv output [b][29][50x50]

__device__ __forceinline__ unsigned su32(const void* p) {
    return (unsigned)__cvta_generic_to_shared(p);
}

// ---------------------------------------------------------------------------
// Kernel A: 5x5 stride-5 spatial conv on frames 31..59 — DIRECT, no smem.
// 1 thread = 1 output pixel; fully coalesced; every input byte read once;
// MLP=25 per thread; zero barriers -> uniform DRAM demand. (R9 verbatim.)
// ---------------------------------------------------------------------------
__global__ void __launch_bounds__(256) kA(const float* __restrict__ x,
                                          const float* __restrict__ sw)
{
    const int id = blockIdx.x * 256 + threadIdx.x;
    if (id >= N_OUT) return;

    const int ocol = id % 50;
    const int orow = (id / 50) % 50;
    const int f    = id / 2500;             // 0..463 = b*29 + dIdx
    const int b    = f / D_NEED;
    const int dIdx = f % D_NEED;

    const float* p = x + (size_t)(b * 60 + D_OFF + dIdx) * 62500u
                       + orow * 1250 + ocol * 5;

    float v[25];
    #pragma unroll
    for (int i = 0; i < 5; i++)
        #pragma unroll
        for (int j = 0; j < 5; j++)
            v[i * 5 + j] = __ldg(p + i * 250 + j);

    float a0 = 0.f, a1 = 0.f, a2 = 0.f, a3 = 0.f, a4 = 0.f;
    #pragma unroll
    for (int j = 0; j < 5; j++) {
        a0 = fmaf(sw[0 * 5 + j],  v[0 * 5 + j], a0);
        a1 = fmaf(sw[1 * 5 + j],  v[1 * 5 + j], a1);
        a2 = fmaf(sw[2 * 5 + j],  v[2 * 5 + j], a2);
        a3 = fmaf(sw[3 * 5 + j],  v[3 * 5 + j], a3);
        a4 = fmaf(sw[4 * 5 + j],  v[4 * 5 + j], a4);
    }
    g_s1[id] = ((a0 + a1) + (a2 + a3)) + a4;
}

// ---------------------------------------------------------------------------
// Kernel BC: temporal conv + ReLU + last conv, then a CLUSTER (10 blocks =
// one batch) gathers the 15x100 flat tile into rank-0's smem via DSMEM
// stores; after cluster.sync rank 0 runs the ama/gang cone -> out[b].
// grid = (10, 16), block = 256, cluster = (10,1,1)  [non-portable size].
// No kernel C, no g_flat global, no chip-wide fences.
// ---------------------------------------------------------------------------
__global__ void __launch_bounds__(256) __cluster_dims__(10, 1, 1)
kBC(const float* __restrict__ tw_g,
    const float* __restrict__ lw_g,
    const float* __restrict__ acw,
    const float* __restrict__ akw,
    const float* __restrict__ akb,
    const float* __restrict__ alw,
    const float* __restrict__ gcw,
    const float* __restrict__ gkw,
    const float* __restrict__ gkb,
    const float* __restrict__ gcolw,
    float* __restrict__ out)
{
    __shared__ float sfirst[T_NEED * 250];   // [t][5 rows x 50 cols]
    __shared__ float sflat[T_NEED * 100];    // gather target (used on rank 0)
    __shared__ float tw[15];
    __shared__ float lw[25];
    __shared__ float red[49];
    const int grp = blockIdx.x;   // row-group == cluster rank
    const int b   = blockIdx.y;
    const int tid = threadIdx.x;

    if (tid < 15) tw[tid] = tw_g[tid];
    if (tid >= 32 && tid < 57) lw[tid - 32] = lw_g[tid - 32];
    __syncthreads();

    // temporal conv + relu (g_s1 read exactly once, coalesced)
    if (tid < 250) {
        const float* src = g_s1 + (size_t)b * (D_NEED * 2500) + grp * 250 + tid;
        float v[D_NEED];
        #pragma unroll
        for (int d = 0; d < D_NEED; d++) v[d] = src[d * 2500];
        #pragma unroll
        for (int t = 0; t < T_NEED; t++) {
            float acc = 0.f;
            #pragma unroll
            for (int k = 0; k < 15; k++)
                acc = fmaf(tw[k], v[t + k], acc);
            sfirst[t * 250 + tid] = fmaxf(acc, 0.f);
        }
    }
    __syncthreads();

    // last conv -> DSMEM store into rank 0's sflat
    if (tid < 150) {
        const int t = tid / 10, c = tid % 10;
        const float* p = sfirst + t * 250 + c * 5;
        float acc = 0.f;
        #pragma unroll
        for (int i = 0; i < 5; i++)
            #pragma unroll
            for (int j = 0; j < 5; j++)
                acc = fmaf(lw[i * 5 + j], p[i * 50 + j], acc);

        unsigned laddr = su32(&sflat[t * 100 + grp * 10 + c]);
        unsigned raddr;
        asm volatile("mapa.shared::cluster.u32 %0, %1, 0;"
                     : "=r"(raddr) : "r"(laddr));
        asm volatile("st.shared::cluster.f32 [%0], %1;"
                     :: "r"(raddr), "f"(acc) : "memory");
    }

    // cluster barrier: all DSMEM stores visible to rank 0 afterwards
    asm volatile("barrier.cluster.arrive.aligned;" ::: "memory");
    asm volatile("barrier.cluster.wait.aligned;"   ::: "memory");

    if (grp != 0) return;

    // ---- rank 0: ama/gang cone at t=59 + 49-tap dot ----
    if (tid < 49) {
        const float ac = acw[0], al = alw[0], gc = gcw[0];
        const int ja = 2 * tid;
        const int jg = (2 * tid + 25) % 100;
        float a = akb[0];
        float g = gkb[0];
        #pragma unroll
        for (int k = 0; k < 15; k++) {
            a = fmaf(akw[k], ac * sflat[k * 100 + ja], a);
            g = fmaf(gkw[k], gc * sflat[k * 100 + jg], g);
        }
        const float amo = al / (1.f + expf(-a));
        const float val = 1.f / (1.f + expf(-(g - fabsf(amo))));
        red[tid] = gcolw[tid] * val;
    }
    __syncthreads();

    if (tid == 0) {
        float s = 0.f;
        #pragma unroll
        for (int j = 0; j < 49; j++) s += red[j];
        out[b] = s;
    }
}

// ---------------------------------------------------------------------------
extern "C" void kernel_launch(void* const* d_in, const int* in_sizes, int n_in,
                              void* d_out, int out_size)
{
    const float* x          = (const float*)d_in[0];
    const float* space_w    = (const float*)d_in[1];
    const float* temporal_w = (const float*)d_in[2];
    const float* last_w     = (const float*)d_in[3];
    const float* ama_create = (const float*)d_in[4];
    const float* ama_kern   = (const float*)d_in[5];
    const float* ama_kern_b = (const float*)d_in[6];
    const float* ama_alpha  = (const float*)d_in[7];
    const float* gang_create= (const float*)d_in[8];
    const float* gang_kern  = (const float*)d_in[9];
    const float* gang_kern_b= (const float*)d_in[10];
    const float* gang_col   = (const float*)d_in[11];
    float* out = (float*)d_out;

    // cluster size 10 > 8 -> non-portable cluster size must be allowed
    cudaFuncSetAttribute(kBC, cudaFuncAttributeNonPortableClusterSizeAllowed, 1);

    kA<<<(N_OUT + 255) / 256, 256>>>(x, space_w);

    dim3 gBC(10, NB);
    kBC<<<gBC, 256>>>(temporal_w, last_w,
                      ama_create, ama_kern, ama_kern_b, ama_alpha,
                      gang_create, gang_kern, gang_kern_b, gang_col, out);
}

// round 14
// speedup vs baseline: 1.4409x; 1.0155x over previous
#include <cuda_runtime.h>
#include <math.h>
#include <stdint.h>

#define NB 16
#define D_NEED 29      // frames d = 31..59
#define D_OFF 31
#define T_NEED 15      // t = 45..59

#define N_OUT (NB * D_NEED * 2500)   // 1,160,000 spatial-conv outputs

// scratch (no allocations allowed)
__device__ float g_s1[NB * D_NEED * 2500];   // spatial-conv output [b][29][50x50]

__device__ __forceinline__ unsigned su32(const void* p) {
    return (unsigned)__cvta_generic_to_shared(p);
}

// ---------------------------------------------------------------------------
// Kernel A: 5x5 stride-5 spatial conv on frames 31..59 — DIRECT, no smem.
// 1 thread = 1 output pixel; fully coalesced; every input byte read once;
// MLP=25 per thread; zero barriers -> uniform DRAM demand.
// Executes griddepcontrol.launch_dependents after its store so the PDL
// dependent (kBC) can begin its prologue while kA drains.
// ---------------------------------------------------------------------------
__global__ void __launch_bounds__(256) kA(const float* __restrict__ x,
                                          const float* __restrict__ sw)
{
    const int id = blockIdx.x * 256 + threadIdx.x;
    if (id < N_OUT) {
        const int ocol = id % 50;
        const int orow = (id / 50) % 50;
        const int f    = id / 2500;             // 0..463 = b*29 + dIdx
        const int b    = f / D_NEED;
        const int dIdx = f % D_NEED;

        const float* p = x + (size_t)(b * 60 + D_OFF + dIdx) * 62500u
                           + orow * 1250 + ocol * 5;

        float v[25];
        #pragma unroll
        for (int i = 0; i < 5; i++)
            #pragma unroll
            for (int j = 0; j < 5; j++)
                v[i * 5 + j] = __ldg(p + i * 250 + j);

        float a0 = 0.f, a1 = 0.f, a2 = 0.f, a3 = 0.f, a4 = 0.f;
        #pragma unroll
        for (int j = 0; j < 5; j++) {
            a0 = fmaf(sw[0 * 5 + j],  v[0 * 5 + j], a0);
            a1 = fmaf(sw[1 * 5 + j],  v[1 * 5 + j], a1);
            a2 = fmaf(sw[2 * 5 + j],  v[2 * 5 + j], a2);
            a3 = fmaf(sw[3 * 5 + j],  v[3 * 5 + j], a3);
            a4 = fmaf(sw[4 * 5 + j],  v[4 * 5 + j], a4);
        }
        g_s1[id] = ((a0 + a1) + (a2 + a3)) + a4;
    }
    asm volatile("griddepcontrol.launch_dependents;" ::: "memory");
}

// ---------------------------------------------------------------------------
// Kernel BC: temporal conv + ReLU + last conv, then a CLUSTER (10 blocks =
// one batch) gathers the 15x100 flat tile into rank-0's smem via DSMEM
// stores; after cluster.sync rank 0 runs the ama/gang cone -> out[b].
// grid = (10, 16), block = 256, cluster = (10,1,1)  [non-portable size].
// PDL: prologue (weight loads) runs before griddepcontrol.wait, overlapping
// kA's tail; g_s1 is only read after the wait.
// ---------------------------------------------------------------------------
__global__ void __launch_bounds__(256) __cluster_dims__(10, 1, 1)
kBC(const float* __restrict__ tw_g,
    const float* __restrict__ lw_g,
    const float* __restrict__ acw,
    const float* __restrict__ akw,
    const float* __restrict__ akb,
    const float* __restrict__ alw,
    const float* __restrict__ gcw,
    const float* __restrict__ gkw,
    const float* __restrict__ gkb,
    const float* __restrict__ gcolw,
    float* __restrict__ out)
{
    __shared__ float sfirst[T_NEED * 250];   // [t][5 rows x 50 cols]
    __shared__ float sflat[T_NEED * 100];    // gather target (used on rank 0)
    __shared__ float tw[15];
    __shared__ float lw[25];
    __shared__ float red[49];
    const int grp = blockIdx.x;   // row-group == cluster rank
    const int b   = blockIdx.y;
    const int tid = threadIdx.x;

    // -------- prologue: independent of kA's output --------
    if (tid < 15) tw[tid] = tw_g[tid];
    if (tid >= 32 && tid < 57) lw[tid - 32] = lw_g[tid - 32];
    __syncthreads();

    // -------- wait for kA's g_s1 writes --------
    asm volatile("griddepcontrol.wait;" ::: "memory");

    // temporal conv + relu (g_s1 read exactly once, coalesced)
    if (tid < 250) {
        const float* src = g_s1 + (size_t)b * (D_NEED * 2500) + grp * 250 + tid;
        float v[D_NEED];
        #pragma unroll
        for (int d = 0; d < D_NEED; d++) v[d] = src[d * 2500];
        #pragma unroll
        for (int t = 0; t < T_NEED; t++) {
            float acc = 0.f;
            #pragma unroll
            for (int k = 0; k < 15; k++)
                acc = fmaf(tw[k], v[t + k], acc);
            sfirst[t * 250 + tid] = fmaxf(acc, 0.f);
        }
    }
    __syncthreads();

    // last conv -> DSMEM store into rank 0's sflat
    if (tid < 150) {
        const int t = tid / 10, c = tid % 10;
        const float* p = sfirst + t * 250 + c * 5;
        float acc = 0.f;
        #pragma unroll
        for (int i = 0; i < 5; i++)
            #pragma unroll
            for (int j = 0; j < 5; j++)
                acc = fmaf(lw[i * 5 + j], p[i * 50 + j], acc);

        unsigned laddr = su32(&sflat[t * 100 + grp * 10 + c]);
        unsigned raddr;
        asm volatile("mapa.shared::cluster.u32 %0, %1, 0;"
                     : "=r"(raddr) : "r"(laddr));
        asm volatile("st.shared::cluster.f32 [%0], %1;"
                     :: "r"(raddr), "f"(acc) : "memory");
    }

    // cluster barrier: all DSMEM stores visible to rank 0 afterwards
    asm volatile("barrier.cluster.arrive.aligned;" ::: "memory");
    asm volatile("barrier.cluster.wait.aligned;"   ::: "memory");

    if (grp != 0) return;

    // ---- rank 0: ama/gang cone at t=59 + 49-tap dot ----
    if (tid < 49) {
        const float ac = acw[0], al = alw[0], gc = gcw[0];
        const int ja = 2 * tid;
        const int jg = (2 * tid + 25) % 100;
        float a = akb[0];
        float g = gkb[0];
        #pragma unroll
        for (int k = 0; k < 15; k++) {
            a = fmaf(akw[k], ac * sflat[k * 100 + ja], a);
            g = fmaf(gkw[k], gc * sflat[k * 100 + jg], g);
        }
        const float amo = al / (1.f + expf(-a));
        const float val = 1.f / (1.f + expf(-(g - fabsf(amo))));
        red[tid] = gcolw[tid] * val;
    }
    __syncthreads();

    if (tid == 0) {
        float s = 0.f;
        #pragma unroll
        for (int j = 0; j < 49; j++) s += red[j];
        out[b] = s;
    }
}

// ---------------------------------------------------------------------------
extern "C" void kernel_launch(void* const* d_in, const int* in_sizes, int n_in,
                              void* d_out, int out_size)
{
    const float* x          = (const float*)d_in[0];
    const float* space_w    = (const float*)d_in[1];
    const float* temporal_w = (const float*)d_in[2];
    const float* last_w     = (const float*)d_in[3];
    const float* ama_create = (const float*)d_in[4];
    const float* ama_kern   = (const float*)d_in[5];
    const float* ama_kern_b = (const float*)d_in[6];
    const float* ama_alpha  = (const float*)d_in[7];
    const float* gang_create= (const float*)d_in[8];
    const float* gang_kern  = (const float*)d_in[9];
    const float* gang_kern_b= (const float*)d_in[10];
    const float* gang_col   = (const float*)d_in[11];
    float* out = (float*)d_out;

    // cluster size 10 > 8 -> non-portable cluster size must be allowed
    cudaFuncSetAttribute(kBC, cudaFuncAttributeNonPortableClusterSizeAllowed, 1);

    kA<<<(N_OUT + 255) / 256, 256>>>(x, space_w);

    // PDL launch of kBC: overlaps its prologue with kA's drain
    cudaLaunchConfig_t cfg = {};
    cfg.gridDim  = dim3(10, NB);
    cfg.blockDim = dim3(256);
    cudaLaunchAttribute attrs[1];
    attrs[0].id = cudaLaunchAttributeProgrammaticStreamSerialization;
    attrs[0].val.programmaticStreamSerializationAllowed = 1;
    cfg.attrs = attrs;
    cfg.numAttrs = 1;
    cudaLaunchKernelEx(&cfg, kBC, temporal_w, last_w,
                       ama_create, ama_kern, ama_kern_b, ama_alpha,
                       gang_create, gang_kern, gang_kern_b, gang_col, out);
}